// round 13
// baseline (speedup 1.0000x reference)
#include <cuda_runtime.h>
#include <cuda_fp16.h>
#include <cstdint>
#include <cstddef>

#define NB 32
#define NN 512
#define NL 64
#define NC 64
#define NF 192

// ---------------- scratch ----------------
__device__ float g_T2[NN * NN];
__device__ __half g_z0h[(size_t)NB * 64 * NN * NL];        // [b][o][n][l] fp16 (k=0 term)
__device__ __half g_zf[(size_t)NB * 2 * 64 * NN * NL];     // [b][kp][o][n][l] fp16
__device__ __half g_Af[(size_t)NB * NN * 1024];            // [b][q][n'] fp16
__device__ __half g_Wf[NF * 64];                           // [f=k*64+o][c] fp16

// ---------------- helpers ----------------
__device__ __forceinline__ uint32_t smem_u32(const void* p) {
    uint32_t a;
    asm("{ .reg .u64 t; cvta.to.shared.u64 t, %1; cvt.u32.u64 %0, t; }" : "=r"(a) : "l"(p));
    return a;
}
__device__ __forceinline__ void cp16(uint32_t dst, const void* src) {
    asm volatile("cp.async.cg.shared.global [%0], [%1], 16;" :: "r"(dst), "l"(src));
}
__device__ __forceinline__ unsigned short to_h(float v) {
    __half hb = __float2half_rn(v);
    return *reinterpret_cast<unsigned short*>(&hb);
}
__device__ __forceinline__ void ldm4(uint32_t addr, uint32_t* r) {
    asm volatile("ldmatrix.sync.aligned.m8n8.x4.shared.b16 {%0,%1,%2,%3}, [%4];"
                 : "=r"(r[0]), "=r"(r[1]), "=r"(r[2]), "=r"(r[3]) : "r"(addr));
}
__device__ __forceinline__ void ldm4t(uint32_t addr, uint32_t* r) {
    asm volatile("ldmatrix.sync.aligned.m8n8.x4.trans.shared.b16 {%0,%1,%2,%3}, [%4];"
                 : "=r"(r[0]), "=r"(r[1]), "=r"(r[2]), "=r"(r[3]) : "r"(addr));
}
__device__ __forceinline__ void mma16816(float* d, const uint32_t* a, const uint32_t* b) {
    asm volatile(
        "mma.sync.aligned.m16n8k16.row.col.f32.f16.f16.f32 "
        "{%0,%1,%2,%3}, {%4,%5,%6,%7}, {%8,%9}, {%0,%1,%2,%3};"
        : "+f"(d[0]), "+f"(d[1]), "+f"(d[2]), "+f"(d[3])
        : "r"(a[0]), "r"(a[1]), "r"(a[2]), "r"(a[3]), "r"(b[0]), "r"(b[1]));
}

// ---------------------------------------------------------------------------
// K1: T2 = 2*adj@adj - I
// ---------------------------------------------------------------------------
__global__ void k1_T2(const float* __restrict__ adj) {
    __shared__ float As[16][16];
    __shared__ float Bs[16][17];
    const int tx = threadIdx.x, ty = threadIdx.y;
    const int q = blockIdx.y * 16 + ty;
    const int n = blockIdx.x * 16 + tx;
    float acc = 0.f;
    for (int t0 = 0; t0 < NN; t0 += 16) {
        As[ty][tx] = adj[(size_t)q * NN + t0 + tx];
        Bs[ty][tx] = adj[(size_t)(t0 + ty) * NN + n];
        __syncthreads();
#pragma unroll
        for (int j = 0; j < 16; j++) acc = fmaf(As[ty][j], Bs[j][tx], acc);
        __syncthreads();
    }
    g_T2[(size_t)q * NN + n] = 2.f * acc - (q == n ? 1.f : 0.f);
}

// ---------------------------------------------------------------------------
// kA: A[b][q][n'] = ds[b][q][n]*(n'<512 ? adj : T2)[q][n] -> fp16
// ---------------------------------------------------------------------------
__global__ __launch_bounds__(256) void kA(const float* __restrict__ ds,
                                          const float* __restrict__ adj) {
    const int q = blockIdx.x, b = blockIdx.y, t = threadIdx.x;
    const int n4 = t * 4, n = n4 & 511;
    const float* mrow = (n4 < 512 ? adj : g_T2) + (size_t)q * NN + n;
    float4 m = *(const float4*)mrow;
    float4 d = *(const float4*)(ds + ((size_t)b * NN + q) * NN + n);
    unsigned short h[4] = {to_h(d.x * m.x), to_h(d.y * m.y),
                           to_h(d.z * m.z), to_h(d.w * m.w)};
    size_t off = ((size_t)b * NN + q) * 1024 + n4;
    *(uint2*)&g_Af[off] = make_uint2((uint32_t)h[0] | ((uint32_t)h[1] << 16),
                                     (uint32_t)h[2] | ((uint32_t)h[3] << 16));
}

// ---------------------------------------------------------------------------
// kW: W -> fp16, row f = k*64+o, col c.  Wr[f][c]=W[o*192+c*3+k]
// ---------------------------------------------------------------------------
__global__ void kW(const float* __restrict__ W) {
    int idx = blockIdx.x * 256 + threadIdx.x;
    if (idx >= NF * 16) return;
    int f = idx >> 4, c4 = (idx & 15) * 4;
    int k = f >> 6, o = f & 63;
    unsigned short h[4];
#pragma unroll
    for (int j = 0; j < 4; j++) h[j] = to_h(W[o * NF + (c4 + j) * 3 + k]);
    *(uint2*)&g_Wf[f * 64 + c4] = make_uint2((uint32_t)h[0] | ((uint32_t)h[1] << 16),
                                             (uint32_t)h[2] | ((uint32_t)h[3] << 16));
}

// ---------------------------------------------------------------------------
// K2 (mma): per CTA a 256-m strip; W resident, x single fp16 (1 MMA term).
// Output staged through smem for fully-coalesced 128B row stores.
// ---------------------------------------------------------------------------
#define K2_W 0
#define K2_XBASE 27648
#define K2_XSTRIDE 9216           // per buffer: X (64 rows x 144B)
#define K2_ST 46080               // staging: 192 rows x 144B
#define K2_SMEM 73728

__global__ __launch_bounds__(256, 2) void k2_mma(const float* __restrict__ x) {
    extern __shared__ __align__(128) char smem[];
    const uint32_t sb = smem_u32(smem);
    const int t = threadIdx.x, lane = t & 31, wid = t >> 5;
    const int mT = blockIdx.x * 256, b = blockIdx.y;

#pragma unroll
    for (int i = 0; i < 6; i++) {
        int idx = t + i * 256, r = idx >> 3, sg8 = idx & 7;
        cp16(sb + K2_W + r * 144 + sg8 * 16, (const char*)g_Wf + r * 128 + sg8 * 16);
    }
    asm volatile("cp.async.commit_group;");
    asm volatile("cp.async.wait_group 0;" ::: "memory");

    const int warpM = wid >> 1, warpN = wid & 1;
    const int lr = lane & 7, seg = lane >> 3;
    const int group = lane >> 2, tig = lane & 3;

    const int sg = t & 15, cbase = t >> 4;
    const float* xb_ptr = x + (size_t)b * NC * 32768 + sg * 4;

    float4 xr[4];
#pragma unroll
    for (int i = 0; i < 4; i++)
        xr[i] = *(const float4*)(xb_ptr + ((size_t)(cbase + 16 * i)) * 32768 + mT);

    for (int sub = 0; sub < 4; sub++) {
        const uint32_t xbuf = sb + K2_XBASE + (sub & 1) * K2_XSTRIDE;
#pragma unroll
        for (int i = 0; i < 4; i++) {
            int c = cbase + 16 * i;
            unsigned short h[4] = {to_h(xr[i].x), to_h(xr[i].y),
                                   to_h(xr[i].z), to_h(xr[i].w)};
            *(uint2*)(smem + (xbuf - sb) + c * 144 + sg * 8) =
                make_uint2((uint32_t)h[0] | ((uint32_t)h[1] << 16),
                           (uint32_t)h[2] | ((uint32_t)h[3] << 16));
        }
        __syncthreads();
        if (sub < 3) {
#pragma unroll
            for (int i = 0; i < 4; i++)
                xr[i] = *(const float4*)(xb_ptr + ((size_t)(cbase + 16 * i)) * 32768 +
                                         mT + (sub + 1) * 64);
        }

        float d[3][4][4];
#pragma unroll
        for (int i = 0; i < 3; i++)
#pragma unroll
            for (int j = 0; j < 4; j++)
#pragma unroll
                for (int e = 0; e < 4; e++) d[i][j][e] = 0.f;

#pragma unroll
        for (int s = 0; s < 4; s++) {
            uint32_t a[3][4], bh[4][2];
#pragma unroll
            for (int mf = 0; mf < 3; mf++) {
                uint32_t row = warpM * 48 + mf * 16 + lr + (seg & 1) * 8;
                uint32_t col = (seg >> 1) * 16 + s * 32;
                ldm4(sb + K2_W + row * 144 + col, a[mf]);
            }
#pragma unroll
            for (int g = 0; g < 2; g++) {
                uint32_t row = s * 16 + lr + (seg & 1) * 8;
                uint32_t col = warpN * 64 + g * 32 + (seg >> 1) * 16;
                uint32_t r4[4];
                ldm4t(xbuf + row * 144 + col, r4);
                bh[g * 2][0] = r4[0]; bh[g * 2][1] = r4[1];
                bh[g * 2 + 1][0] = r4[2]; bh[g * 2 + 1][1] = r4[3];
            }
#pragma unroll
            for (int mf = 0; mf < 3; mf++)
#pragma unroll
                for (int nf = 0; nf < 4; nf++)
                    mma16816(d[mf][nf], a[mf], bh[nf]);
        }

        // stage fragments (bank-conflict-free: word = 36f + tig pattern)
#pragma unroll
        for (int mf = 0; mf < 3; mf++)
#pragma unroll
            for (int half = 0; half < 2; half++) {
                int f = warpM * 48 + mf * 16 + group + half * 8;
#pragma unroll
                for (int nf = 0; nf < 4; nf++) {
                    int ml = warpN * 32 + nf * 8 + tig * 2;
                    float c0 = d[mf][nf][half * 2], c1 = d[mf][nf][half * 2 + 1];
                    *(uint32_t*)(smem + K2_ST + f * 144 + ml * 2) =
                        (uint32_t)to_h(c0) | ((uint32_t)to_h(c1) << 16);
                }
            }
        __syncthreads();

        // coalesced 128B row stores
        const int m0 = mT + sub * 64;
#pragma unroll
        for (int i = 0; i < 6; i++) {
            int idx = t + i * 256;              // 0..1535
            int r = idx >> 3, u = idx & 7;
            uint4 v = *(const uint4*)(smem + K2_ST + r * 144 + u * 16);
            int k = r >> 6, o = r & 63;
            char* dst;
            if (k == 0) dst = (char*)&g_z0h[(size_t)(b * 64 + o) * 32768 + m0];
            else        dst = (char*)&g_zf[(size_t)((b * 2 + k - 1) * 64 + o) * 32768 + m0];
            *(uint4*)(dst + u * 16) = v;
        }
        // stage reuse protected by next iteration's __syncthreads
    }
}

// ---------------------------------------------------------------------------
// K3: fp16 mma GEMM, single term.  CTA 128(q) x 128(col), K=1024 in 32-n
// chunks, 3-stage cp.async ring.  Epilogue staged through smem (fp32, 2
// passes) for fully-coalesced out stores.
// ---------------------------------------------------------------------------
#define OFF_A 0
#define OFF_B 10240
#define STAGEB 18944              // A 128x80 + B 32x272
#define SMEM_K3 (3 * STAGEB)
#define K3_ST_RS 544              // 64 rows x 544B staging (fits in ring smem)

__device__ __forceinline__ void k3_load(uint32_t sb, int b, int q0, int o0,
                                        int stg, int kk) {
    const int t = threadIdx.x;
    const uint32_t st = sb + stg * STAGEB;
    const int kp = kk >> 4, n0 = (kk & 15) * 32;
#pragma unroll
    for (int i = 0; i < 2; i++) {
        int idx = t + i * 256;
        int r = idx >> 2, u = (idx & 3) * 16;
        cp16(st + OFF_A + r * 80 + u,
             (const char*)g_Af + ((size_t)(b * NN + q0 + r)) * 2048 + kk * 64 + u);
    }
#pragma unroll
    for (int i = 0; i < 2; i++) {
        int idx = t + i * 256, nl = idx >> 4, sg = idx & 15;
        int ol = sg >> 3, l16 = (sg & 7) * 16;
        size_t src = ((size_t)((b * 2 + kp) * 64 + o0 + ol) * 512 + n0 + nl) * 128 + l16;
        cp16(st + OFF_B + nl * 272 + sg * 16, (const char*)g_zf + src);
    }
}

__global__ __launch_bounds__(256, 2) void k3_main(const float* __restrict__ ds,
                                                  const float* __restrict__ bias,
                                                  float* __restrict__ out) {
    extern __shared__ __align__(128) char smem[];
    const uint32_t sb = smem_u32(smem);
    const int t = threadIdx.x, lane = t & 31, wid = t >> 5;
    const int q0 = blockIdx.x * 128, b = blockIdx.z;
    const int o0 = blockIdx.y * 2;
    const int warpM = wid >> 2, warpN = wid & 3;
    const int lr = lane & 7, seg = lane >> 3;

    float d[4][4][4];
#pragma unroll
    for (int m = 0; m < 4; m++)
#pragma unroll
        for (int n = 0; n < 4; n++)
#pragma unroll
            for (int e = 0; e < 4; e++) d[m][n][e] = 0.f;

    k3_load(sb, b, q0, o0, 0, 0);
    asm volatile("cp.async.commit_group;");
    k3_load(sb, b, q0, o0, 1, 1);
    asm volatile("cp.async.commit_group;");
    k3_load(sb, b, q0, o0, 2, 2);
    asm volatile("cp.async.commit_group;");

    int cur = 0;
    for (int kk = 0; kk < 32; kk++) {
        if (kk < 30)       asm volatile("cp.async.wait_group 2;" ::: "memory");
        else if (kk == 30) asm volatile("cp.async.wait_group 1;" ::: "memory");
        else               asm volatile("cp.async.wait_group 0;" ::: "memory");
        __syncthreads();
        const uint32_t st = sb + cur * STAGEB;
#pragma unroll
        for (int s = 0; s < 2; s++) {
            uint32_t bh[4][2], a[4][4];
#pragma unroll
            for (int g = 0; g < 2; g++) {
                uint32_t row = s * 16 + lr + (seg & 1) * 8;
                uint32_t col = warpN * 64 + g * 32 + (seg >> 1) * 16;
                uint32_t r4[4];
                ldm4t(st + OFF_B + row * 272 + col, r4);
                bh[g * 2][0] = r4[0]; bh[g * 2][1] = r4[1];
                bh[g * 2 + 1][0] = r4[2]; bh[g * 2 + 1][1] = r4[3];
            }
#pragma unroll
            for (int mf = 0; mf < 4; mf++) {
                uint32_t row = warpM * 64 + mf * 16 + lr + (seg & 1) * 8;
                ldm4(st + OFF_A + row * 80 + (seg >> 1) * 16 + s * 32, a[mf]);
            }
#pragma unroll
            for (int mf = 0; mf < 4; mf++)
#pragma unroll
                for (int nf = 0; nf < 4; nf++)
                    mma16816(d[mf][nf], a[mf], bh[nf]);
        }
        __syncthreads();
        if (kk < 29) {
            k3_load(sb, b, q0, o0, cur, kk + 3);
            asm volatile("cp.async.commit_group;");
        }
        cur = (cur == 2) ? 0 : cur + 1;
    }

    // Epilogue: + bias + ds[q,q]*z0, staged fp32 (2 passes of 64 q-rows)
    const int group = lane >> 2, tig = lane & 3;
#pragma unroll
    for (int pass = 0; pass < 2; pass++) {
        if (warpM == pass) {
#pragma unroll
            for (int mf = 0; mf < 4; mf++)
#pragma unroll
                for (int half = 0; half < 2; half++) {
                    const int qlp = mf * 16 + group + half * 8;      // 0..63
                    const int q = q0 + pass * 64 + qlp;
                    const float dqq = ds[((size_t)b * NN + q) * NN + q];
#pragma unroll
                    for (int nf = 0; nf < 4; nf++) {
                        const int colg = warpN * 32 + nf * 8 + tig * 2;  // 0..127
                        const int o = o0 + (colg >> 6), l = colg & 63;
                        const float bo = bias[o];
                        uint32_t zp = *(const uint32_t*)&g_z0h[
                            (size_t)(b * 64 + o) * 32768 + (size_t)q * 64 + l];
                        float2 z0 = __half22float2(*reinterpret_cast<__half2*>(&zp));
                        float2 r;
                        r.x = fmaf(dqq, z0.x, d[mf][nf][half * 2 + 0] + bo);
                        r.y = fmaf(dqq, z0.y, d[mf][nf][half * 2 + 1] + bo);
                        *(float2*)(smem + qlp * K3_ST_RS + colg * 4) = r;
                    }
                }
        }
        __syncthreads();
        // coalesced copy: 64 rows x 512B -> out
#pragma unroll
        for (int i = 0; i < 8; i++) {
            int c = t + i * 256;                 // 0..2047
            int ql = c >> 5, col4 = (c & 31) * 4;
            int ol = col4 >> 6, l = col4 & 63;
            float4 v = *(const float4*)(smem + ql * K3_ST_RS + col4 * 4);
            *(float4*)&out[(((size_t)(b * NC + o0 + ol)) * NN +
                            q0 + pass * 64 + ql) * 64 + l] = v;
        }
        __syncthreads();
    }
}

// ---------------------------------------------------------------------------
extern "C" void kernel_launch(void* const* d_in, const int* in_sizes, int n_in,
                              void* d_out, int out_size) {
    const float* x    = (const float*)d_in[0];
    const float* adj  = (const float*)d_in[1];
    const float* ds   = (const float*)d_in[2];
    const float* W    = (const float*)d_in[3];
    const float* bias = (const float*)d_in[4];
    float* out = (float*)d_out;

    cudaFuncSetAttribute(k2_mma, cudaFuncAttributeMaxDynamicSharedMemorySize, K2_SMEM);
    cudaFuncSetAttribute(k3_main, cudaFuncAttributeMaxDynamicSharedMemorySize, SMEM_K3);

    k1_T2<<<dim3(32, 32), dim3(16, 16)>>>(adj);
    kA<<<dim3(512, 32), 256>>>(ds, adj);
    kW<<<12, 256>>>(W);
    k2_mma<<<dim3(128, 32), 256, K2_SMEM>>>(x);
    k3_main<<<dim3(4, 32, 32), 256, SMEM_K3>>>(ds, bias, out);
}

// round 17
// speedup vs baseline: 1.1675x; 1.1675x over previous
#include <cuda_runtime.h>
#include <cuda_fp16.h>
#include <cstdint>
#include <cstddef>

#define NB 32
#define NN 512
#define NL 64
#define NC 64
#define NF 192

// ---------------- scratch ----------------
__device__ float g_T2[NN * NN];
__device__ __half g_z0h[(size_t)NB * 64 * NN * NL];        // [b][o][n][l] fp16 (k=0 term)
__device__ __half g_zf[(size_t)NB * 2 * 64 * NN * NL];     // [b][kp][o][n][l] fp16
__device__ __half g_Af[(size_t)NB * NN * 1024];            // [b][q][n'] fp16
__device__ __half g_Wf[NF * 64];                           // [f=k*64+o][c] fp16

// ---------------- helpers ----------------
__device__ __forceinline__ uint32_t smem_u32(const void* p) {
    uint32_t a;
    asm("{ .reg .u64 t; cvta.to.shared.u64 t, %1; cvt.u32.u64 %0, t; }" : "=r"(a) : "l"(p));
    return a;
}
__device__ __forceinline__ void cp16(uint32_t dst, const void* src) {
    asm volatile("cp.async.cg.shared.global [%0], [%1], 16;" :: "r"(dst), "l"(src));
}
__device__ __forceinline__ unsigned short to_h(float v) {
    __half hb = __float2half_rn(v);
    return *reinterpret_cast<unsigned short*>(&hb);
}
__device__ __forceinline__ void ldm4(uint32_t addr, uint32_t* r) {
    asm volatile("ldmatrix.sync.aligned.m8n8.x4.shared.b16 {%0,%1,%2,%3}, [%4];"
                 : "=r"(r[0]), "=r"(r[1]), "=r"(r[2]), "=r"(r[3]) : "r"(addr));
}
__device__ __forceinline__ void ldm4t(uint32_t addr, uint32_t* r) {
    asm volatile("ldmatrix.sync.aligned.m8n8.x4.trans.shared.b16 {%0,%1,%2,%3}, [%4];"
                 : "=r"(r[0]), "=r"(r[1]), "=r"(r[2]), "=r"(r[3]) : "r"(addr));
}
__device__ __forceinline__ void mma16816(float* d, const uint32_t* a, const uint32_t* b) {
    asm volatile(
        "mma.sync.aligned.m16n8k16.row.col.f32.f16.f16.f32 "
        "{%0,%1,%2,%3}, {%4,%5,%6,%7}, {%8,%9}, {%0,%1,%2,%3};"
        : "+f"(d[0]), "+f"(d[1]), "+f"(d[2]), "+f"(d[3])
        : "r"(a[0]), "r"(a[1]), "r"(a[2]), "r"(a[3]), "r"(b[0]), "r"(b[1]));
}

// ---------------------------------------------------------------------------
// K1: T2 = 2*adj@adj - I
// ---------------------------------------------------------------------------
__global__ void k1_T2(const float* __restrict__ adj) {
    __shared__ float As[16][16];
    __shared__ float Bs[16][17];
    const int tx = threadIdx.x, ty = threadIdx.y;
    const int q = blockIdx.y * 16 + ty;
    const int n = blockIdx.x * 16 + tx;
    float acc = 0.f;
    for (int t0 = 0; t0 < NN; t0 += 16) {
        As[ty][tx] = adj[(size_t)q * NN + t0 + tx];
        Bs[ty][tx] = adj[(size_t)(t0 + ty) * NN + n];
        __syncthreads();
#pragma unroll
        for (int j = 0; j < 16; j++) acc = fmaf(As[ty][j], Bs[j][tx], acc);
        __syncthreads();
    }
    g_T2[(size_t)q * NN + n] = 2.f * acc - (q == n ? 1.f : 0.f);
}

// ---------------------------------------------------------------------------
// kA: A[b][q][n'] = ds[b][q][n]*(n'<512 ? adj : T2)[q][n] -> fp16
// ---------------------------------------------------------------------------
__global__ __launch_bounds__(256) void kA(const float* __restrict__ ds,
                                          const float* __restrict__ adj) {
    const int q = blockIdx.x, b = blockIdx.y, t = threadIdx.x;
    const int n4 = t * 4, n = n4 & 511;
    const float* mrow = (n4 < 512 ? adj : g_T2) + (size_t)q * NN + n;
    float4 m = *(const float4*)mrow;
    float4 d = *(const float4*)(ds + ((size_t)b * NN + q) * NN + n);
    unsigned short h[4] = {to_h(d.x * m.x), to_h(d.y * m.y),
                           to_h(d.z * m.z), to_h(d.w * m.w)};
    size_t off = ((size_t)b * NN + q) * 1024 + n4;
    *(uint2*)&g_Af[off] = make_uint2((uint32_t)h[0] | ((uint32_t)h[1] << 16),
                                     (uint32_t)h[2] | ((uint32_t)h[3] << 16));
}

// ---------------------------------------------------------------------------
// kW: W -> fp16, row f = k*64+o, col c.  Wr[f][c]=W[o*192+c*3+k]
// ---------------------------------------------------------------------------
__global__ void kW(const float* __restrict__ W) {
    int idx = blockIdx.x * 256 + threadIdx.x;
    if (idx >= NF * 16) return;
    int f = idx >> 4, c4 = (idx & 15) * 4;
    int k = f >> 6, o = f & 63;
    unsigned short h[4];
#pragma unroll
    for (int j = 0; j < 4; j++) h[j] = to_h(W[o * NF + (c4 + j) * 3 + k]);
    *(uint2*)&g_Wf[f * 64 + c4] = make_uint2((uint32_t)h[0] | ((uint32_t)h[1] << 16),
                                             (uint32_t)h[2] | ((uint32_t)h[3] << 16));
}

// ---------------------------------------------------------------------------
// K2 (mma): per CTA a 256-m strip; W resident, x single fp16 (1 MMA term).
// (R11 version — the 675us baseline; R12 staging reverted)
// ---------------------------------------------------------------------------
#define K2_W 0
#define K2_XBASE 27648
#define K2_XSTRIDE 9216           // per buffer: X (64 rows x 144B)
#define K2_SMEM 46080

__global__ __launch_bounds__(256, 2) void k2_mma(const float* __restrict__ x) {
    extern __shared__ __align__(128) char smem[];
    const uint32_t sb = smem_u32(smem);
    const int t = threadIdx.x, lane = t & 31, wid = t >> 5;
    const int mT = blockIdx.x * 256, b = blockIdx.y;

#pragma unroll
    for (int i = 0; i < 6; i++) {
        int idx = t + i * 256, r = idx >> 3, sg8 = idx & 7;
        cp16(sb + K2_W + r * 144 + sg8 * 16, (const char*)g_Wf + r * 128 + sg8 * 16);
    }
    asm volatile("cp.async.commit_group;");
    asm volatile("cp.async.wait_group 0;" ::: "memory");

    const int warpM = wid >> 1, warpN = wid & 1;
    const int lr = lane & 7, seg = lane >> 3;
    const int group = lane >> 2, tig = lane & 3;

    const int sg = t & 15, cbase = t >> 4;
    const float* xb_ptr = x + (size_t)b * NC * 32768 + sg * 4;

    float4 xr[4];
#pragma unroll
    for (int i = 0; i < 4; i++)
        xr[i] = *(const float4*)(xb_ptr + ((size_t)(cbase + 16 * i)) * 32768 + mT);

    for (int sub = 0; sub < 4; sub++) {
        const uint32_t xbuf = sb + K2_XBASE + (sub & 1) * K2_XSTRIDE;
#pragma unroll
        for (int i = 0; i < 4; i++) {
            int c = cbase + 16 * i;
            unsigned short h[4] = {to_h(xr[i].x), to_h(xr[i].y),
                                   to_h(xr[i].z), to_h(xr[i].w)};
            *(uint2*)(smem + (xbuf - sb) + c * 144 + sg * 8) =
                make_uint2((uint32_t)h[0] | ((uint32_t)h[1] << 16),
                           (uint32_t)h[2] | ((uint32_t)h[3] << 16));
        }
        __syncthreads();
        if (sub < 3) {
#pragma unroll
            for (int i = 0; i < 4; i++)
                xr[i] = *(const float4*)(xb_ptr + ((size_t)(cbase + 16 * i)) * 32768 +
                                         mT + (sub + 1) * 64);
        }

        float d[3][4][4];
#pragma unroll
        for (int i = 0; i < 3; i++)
#pragma unroll
            for (int j = 0; j < 4; j++)
#pragma unroll
                for (int e = 0; e < 4; e++) d[i][j][e] = 0.f;

#pragma unroll
        for (int s = 0; s < 4; s++) {
            uint32_t a[3][4], bh[4][2];
#pragma unroll
            for (int mf = 0; mf < 3; mf++) {
                uint32_t row = warpM * 48 + mf * 16 + lr + (seg & 1) * 8;
                uint32_t col = (seg >> 1) * 16 + s * 32;
                ldm4(sb + K2_W + row * 144 + col, a[mf]);
            }
#pragma unroll
            for (int g = 0; g < 2; g++) {
                uint32_t row = s * 16 + lr + (seg & 1) * 8;
                uint32_t col = warpN * 64 + g * 32 + (seg >> 1) * 16;
                uint32_t r4[4];
                ldm4t(xbuf + row * 144 + col, r4);
                bh[g * 2][0] = r4[0]; bh[g * 2][1] = r4[1];
                bh[g * 2 + 1][0] = r4[2]; bh[g * 2 + 1][1] = r4[3];
            }
#pragma unroll
            for (int mf = 0; mf < 3; mf++)
#pragma unroll
                for (int nf = 0; nf < 4; nf++)
                    mma16816(d[mf][nf], a[mf], bh[nf]);
        }

        const int m0 = mT + sub * 64;
#pragma unroll
        for (int mf = 0; mf < 3; mf++)
#pragma unroll
            for (int half = 0; half < 2; half++) {
                int f = warpM * 48 + mf * 16 + group + half * 8;
                int k = f >> 6, o = f & 63;
#pragma unroll
                for (int nf = 0; nf < 4; nf++) {
                    int m = m0 + warpN * 32 + nf * 8 + tig * 2;
                    float c0 = d[mf][nf][half * 2], c1 = d[mf][nf][half * 2 + 1];
                    uint32_t pk = (uint32_t)to_h(c0) | ((uint32_t)to_h(c1) << 16);
                    if (k == 0) {
                        *(uint32_t*)&g_z0h[(size_t)(b * 64 + o) * 32768 + m] = pk;
                    } else {
                        *(uint32_t*)&g_zf[(size_t)((b * 2 + k - 1) * 64 + o) * 32768 + m] = pk;
                    }
                }
            }
    }
}

// ---------------------------------------------------------------------------
// K3: fp16 mma GEMM, single term.  CTA 128(q) x 256(col = 4o x 64l), K=1024
// in 32-n chunks, 3-stage cp.async ring.  Warps 2(M) x 4(N), 64x64 each.
// ---------------------------------------------------------------------------
#define OFF_A 0
#define OFF_B 10240
#define BROW 528                  // 512B data + 16 pad (528 % 128 == 16: conflict-free)
#define STAGEB (OFF_B + 32 * BROW)  // 10240 + 16896 = 27136
#define SMEM_K3 (3 * STAGEB)        // 81408

__device__ __forceinline__ void k3_load(uint32_t sb, int b, int q0, int o0,
                                        int stg, int kk) {
    const int t = threadIdx.x;
    const uint32_t st = sb + stg * STAGEB;
    const int kp = kk >> 4, n0 = (kk & 15) * 32;
    // A: 128 q-rows x 64B (32 k halves), pad 80
#pragma unroll
    for (int i = 0; i < 2; i++) {
        int idx = t + i * 256;
        int r = idx >> 2, u = (idx & 3) * 16;
        cp16(st + OFF_A + r * 80 + u,
             (const char*)g_Af + ((size_t)(b * NN + q0 + r)) * 2048 + kk * 64 + u);
    }
    // B: 32 n-rows x 512B (4o x 64l halves), pad 528
#pragma unroll
    for (int i = 0; i < 4; i++) {
        int idx = t + i * 256;                  // 0..1023
        int nl = idx >> 5, sg = idx & 31;
        int ol = sg >> 3, l16 = (sg & 7) * 16;
        size_t src = ((size_t)((b * 2 + kp) * 64 + o0 + ol) * 512 + n0 + nl) * 128 + l16;
        cp16(st + OFF_B + nl * BROW + sg * 16, (const char*)g_zf + src);
    }
}

__global__ __launch_bounds__(256, 1) void k3_main(const float* __restrict__ ds,
                                                  const float* __restrict__ bias,
                                                  float* __restrict__ out) {
    extern __shared__ __align__(128) char smem[];
    const uint32_t sb = smem_u32(smem);
    const int t = threadIdx.x, lane = t & 31, wid = t >> 5;
    const int q0 = blockIdx.x * 128, b = blockIdx.z;
    const int o0 = blockIdx.y * 4;
    const int warpM = wid >> 2, warpN = wid & 3;   // 2 x 4, each 64q x 64col
    const int lr = lane & 7, seg = lane >> 3;

    float d[4][8][4];
#pragma unroll
    for (int m = 0; m < 4; m++)
#pragma unroll
        for (int n = 0; n < 8; n++)
#pragma unroll
            for (int e = 0; e < 4; e++) d[m][n][e] = 0.f;

    k3_load(sb, b, q0, o0, 0, 0);
    asm volatile("cp.async.commit_group;");
    k3_load(sb, b, q0, o0, 1, 1);
    asm volatile("cp.async.commit_group;");
    k3_load(sb, b, q0, o0, 2, 2);
    asm volatile("cp.async.commit_group;");

    int cur = 0;
    for (int kk = 0; kk < 32; kk++) {
        if (kk < 30)       asm volatile("cp.async.wait_group 2;" ::: "memory");
        else if (kk == 30) asm volatile("cp.async.wait_group 1;" ::: "memory");
        else               asm volatile("cp.async.wait_group 0;" ::: "memory");
        __syncthreads();
        const uint32_t st = sb + cur * STAGEB;
#pragma unroll
        for (int s = 0; s < 2; s++) {
            uint32_t bh[8][2], a[4][4];
#pragma unroll
            for (int g = 0; g < 4; g++) {
                uint32_t row = s * 16 + lr + (seg & 1) * 8;
                uint32_t col = warpN * 128 + g * 32 + (seg >> 1) * 16;   // bytes
                uint32_t r4[4];
                ldm4t(st + OFF_B + row * BROW + col, r4);
                bh[g * 2][0] = r4[0]; bh[g * 2][1] = r4[1];
                bh[g * 2 + 1][0] = r4[2]; bh[g * 2 + 1][1] = r4[3];
            }
#pragma unroll
            for (int mf = 0; mf < 4; mf++) {
                uint32_t row = warpM * 64 + mf * 16 + lr + (seg & 1) * 8;
                ldm4(st + OFF_A + row * 80 + (seg >> 1) * 16 + s * 32, a[mf]);
            }
#pragma unroll
            for (int mf = 0; mf < 4; mf++)
#pragma unroll
                for (int nf = 0; nf < 8; nf++)
                    mma16816(d[mf][nf], a[mf], bh[nf]);
        }
        __syncthreads();
        if (kk < 29) {
            k3_load(sb, b, q0, o0, cur, kk + 3);
            asm volatile("cp.async.commit_group;");
        }
        cur = (cur == 2) ? 0 : cur + 1;
    }

    // Epilogue: + bias + ds[q,q]*z0 (direct stores, R11-style)
    const int group = lane >> 2, tig = lane & 3;
#pragma unroll
    for (int mf = 0; mf < 4; mf++)
#pragma unroll
        for (int half = 0; half < 2; half++) {
            const int q = q0 + warpM * 64 + mf * 16 + group + half * 8;
            const float dqq = ds[((size_t)b * NN + q) * NN + q];
#pragma unroll
            for (int nf = 0; nf < 8; nf++) {
                const int colg = warpN * 64 + nf * 8 + tig * 2;  // 0..255
                const int o = o0 + (colg >> 6), l = colg & 63;
                const float bo = bias[o];
                uint32_t zp = *(const uint32_t*)&g_z0h[(size_t)(b * 64 + o) * 32768 +
                                                       (size_t)q * 64 + l];
                float2 z0 = __half22float2(*reinterpret_cast<__half2*>(&zp));
                float2 r;
                r.x = fmaf(dqq, z0.x, d[mf][nf][half * 2 + 0] + bo);
                r.y = fmaf(dqq, z0.y, d[mf][nf][half * 2 + 1] + bo);
                *(float2*)&out[(((size_t)(b * NC + o)) * NN + q) * 64 + l] = r;
            }
        }
}

// ---------------------------------------------------------------------------
extern "C" void kernel_launch(void* const* d_in, const int* in_sizes, int n_in,
                              void* d_out, int out_size) {
    const float* x    = (const float*)d_in[0];
    const float* adj  = (const float*)d_in[1];
    const float* ds   = (const float*)d_in[2];
    const float* W    = (const float*)d_in[3];
    const float* bias = (const float*)d_in[4];
    float* out = (float*)d_out;

    cudaFuncSetAttribute(k2_mma, cudaFuncAttributeMaxDynamicSharedMemorySize, K2_SMEM);
    cudaFuncSetAttribute(k3_main, cudaFuncAttributeMaxDynamicSharedMemorySize, SMEM_K3);

    k1_T2<<<dim3(32, 32), dim3(16, 16)>>>(adj);
    kA<<<dim3(512, 32), 256>>>(ds, adj);
    kW<<<12, 256>>>(W);
    k2_mma<<<dim3(128, 32), 256, K2_SMEM>>>(x);
    k3_main<<<dim3(4, 16, 32), 256, SMEM_K3>>>(ds, bias, out);
}